// round 15
// baseline (speedup 1.0000x reference)
#include <cuda_runtime.h>
#include <math.h>
#include <stdint.h>

// Problem constants
#define BATCH 4096
#define NSTEP 20
#define D0 1024
#define D1 2048
#define D2 2048
#define D3 512

// GEMM tiling: 256x128 CTA tile, BK=16, 256 threads, 8 warps (4M x 2N),
// warp tile 64x64 of m16n8k8 tf32 mma. 3-stage cp.async pipeline.
#define TM 256
#define TN 128
#define BK 16
#define STAGES 3
#define ROW_W 20                       // words per smem row (16 data + 4 pad)
#define TILE_A_W (TM * ROW_W)          // 5120 words
#define TILE_B_W (TN * ROW_W)          // 2560 words
#define STAGE_W (TILE_A_W + TILE_B_W)  // 7680 words
#define SMEM_BYTES (STAGES * STAGE_W * 4)   // 92160 B

enum { OP_FWD = 0, OP_ERR = 1, OP_UPD = 2, OP_UPD3 = 3 };

// ---------------- scratch state (allocation-free rule: __device__ globals) ----
__device__ float g_r1[BATCH * D1];
__device__ float g_r2[BATCH * D2];
__device__ float g_r3[BATCH * D3];
__device__ float g_e0[BATCH * D0];
__device__ float g_e1[BATCH * D1];
__device__ float g_e2[BATCH * D2];
// tf32-rounded operand copies
__device__ float g_r1r[BATCH * D1];
__device__ float g_r2r[BATCH * D2];
__device__ float g_r3r[BATCH * D3];
__device__ float g_e0r[BATCH * D0];
__device__ float g_e1r[BATCH * D1];
__device__ float g_e2r[BATCH * D2];
__device__ float g_xr[BATCH * D0];
__device__ float g_W0r[D1 * D0];
__device__ float g_W1r[D2 * D1];
__device__ float g_W2r[D3 * D2];
__device__ float g_WT0r[D0 * D1];
__device__ float g_WT1r[D1 * D2];
__device__ float g_WT2r[D2 * D3];
__device__ float g_acc;

// ---------------- helpers ----------------
__device__ __forceinline__ uint32_t f2tf32(float f)
{
    uint32_t u;
    asm("cvt.rna.tf32.f32 %0, %1;" : "=r"(u) : "f"(f));
    return u;
}

__device__ __forceinline__ float roundtf(float f)
{
    return __uint_as_float(f2tf32(f));
}

__device__ __forceinline__ void mma_tf32(float* c, const uint32_t* a,
                                         uint32_t b0, uint32_t b1)
{
    asm volatile(
        "mma.sync.aligned.m16n8k8.row.col.f32.tf32.tf32.f32 "
        "{%0,%1,%2,%3}, {%4,%5,%6,%7}, {%8,%9}, {%0,%1,%2,%3};"
        : "+f"(c[0]), "+f"(c[1]), "+f"(c[2]), "+f"(c[3])
        : "r"(a[0]), "r"(a[1]), "r"(a[2]), "r"(a[3]), "r"(b0), "r"(b1));
}

__device__ __forceinline__ uint32_t smem_u32(const void* p)
{
    uint32_t a;
    asm("{ .reg .u64 t; cvta.to.shared.u64 t, %1; cvt.u32.u64 %0, t; }"
        : "=r"(a) : "l"(p));
    return a;
}

__device__ __forceinline__ void cp_async16(uint32_t saddr, const void* gaddr)
{
    asm volatile("cp.async.cg.shared.global [%0], [%1], 16;"
                 :: "r"(saddr), "l"(gaddr) : "memory");
}

__device__ __forceinline__ void cp_commit()
{
    asm volatile("cp.async.commit_group;" ::: "memory");
}

__device__ __forceinline__ void cp_wait1()
{
    asm volatile("cp.async.wait_group 1;" ::: "memory");
}

// ---------------- fused NT GEMM: D(4096 x N) = A(4096 x K) @ B(N x K)^T ------
struct Seg {
    const float* A;     // (4096, K) tf32-rounded
    const float* B;     // (N, K)    tf32-rounded
    const float* aux;   // bias (FWD) / fp32 array (ERR/UPD) / unused (UPD3)
    float* Out;         // fp32 output (read-modify for UPD/UPD3)
    float* OutR;        // tf32-rounded copy of output
    int N, K, tileOff, tilesN, op;
};
struct FusedArgs { Seg s[3]; int nseg; };

// Producer mapping: each quarter-warp (8 lanes) writes 8 CONSECUTIVE rows at
// the SAME 16B column j. With ROW_W=20, (row*20)%32 over 8 consecutive rows
// enumerates all 8 bank-quads -> STS conflict-free.
__device__ __forceinline__ void issue_tile(const float* __restrict__ A,
                                           const float* __restrict__ B,
                                           int K, int row0, int col0, int k0,
                                           uint32_t sA, uint32_t sB, int tid)
{
    #pragma unroll
    for (int h = 0; h < 4; h++) {                 // A: 256 rows x 4 chunks
        const int idx = tid + h * 256;            // 0..1023
        const int j = (idx >> 6) & 3;
        const int row = (idx & 63) | ((idx >> 8) << 6);
        cp_async16(sA + (uint32_t)(row * ROW_W + j * 4) * 4,
                   A + (size_t)(row0 + row) * K + k0 + j * 4);
    }
    #pragma unroll
    for (int h = 0; h < 2; h++) {                 // B: 128 rows x 4 chunks
        const int idx = tid + h * 256;            // 0..511
        const int j = (idx >> 6) & 3;
        const int row = (idx & 63) | ((idx >> 8) << 6);
        cp_async16(sB + (uint32_t)(row * ROW_W + j * 4) * 4,
                   B + (size_t)(col0 + row) * K + k0 + j * 4);
    }
}

__global__ __launch_bounds__(256, 1) void gemm_fused(FusedArgs fa)
{
    extern __shared__ float smem[];
    const int bid = blockIdx.x;

    int si = 0;
    if (fa.nseg > 1 && bid >= fa.s[1].tileOff) si = 1;
    if (fa.nseg > 2 && bid >= fa.s[2].tileOff) si = 2;
    const Seg sg = fa.s[si];

    const int tile = bid - sg.tileOff;
    const int tx = tile % sg.tilesN;
    const int ty = tile / sg.tilesN;
    const int row0 = ty * TM;
    const int col0 = tx * TN;
    const int N = sg.N, K = sg.K;
    const int KT = K / BK;

    const int tid  = threadIdx.x;
    const int lane = tid & 31;
    const int w    = tid >> 5;
    const int g    = lane >> 2;
    const int t    = lane & 3;
    const int wm   = (w & 3) * 64;     // warp M offset (4 warps in M)
    const int wn   = (w >> 2) * 64;    // warp N offset (2 warps in N)

    const uint32_t sbase = smem_u32(smem);

    // prologue: issue first STAGES-1 tiles
    #pragma unroll
    for (int s = 0; s < STAGES - 1; s++) {
        issue_tile(sg.A, sg.B, K, row0, col0, s * BK,
                   sbase + (uint32_t)(s * STAGE_W) * 4,
                   sbase + (uint32_t)(s * STAGE_W + TILE_A_W) * 4, tid);
        cp_commit();
    }

    float acc[4][8][4];
    #pragma unroll
    for (int mt = 0; mt < 4; mt++)
        #pragma unroll
        for (int nt = 0; nt < 8; nt++)
            #pragma unroll
            for (int i = 0; i < 4; i++) acc[mt][nt][i] = 0.0f;

    for (int kt = 0; kt < KT; kt++) {
        cp_wait1();
        __syncthreads();

        const int knext = kt + STAGES - 1;
        if (knext < KT) {
            const int sn = knext % STAGES;
            issue_tile(sg.A, sg.B, K, row0, col0, knext * BK,
                       sbase + (uint32_t)(sn * STAGE_W) * 4,
                       sbase + (uint32_t)(sn * STAGE_W + TILE_A_W) * 4, tid);
        }
        cp_commit();

        const int s = kt % STAGES;
        const uint32_t* As = (const uint32_t*)smem + s * STAGE_W;
        const uint32_t* Bs = As + TILE_A_W;

        #pragma unroll
        for (int k8 = 0; k8 < BK / 8; k8++) {
            const int kb = k8 * 8;
            uint32_t af[4][4], bf[8][2];
            #pragma unroll
            for (int mt = 0; mt < 4; mt++) {
                const int m = wm + mt * 16 + g;
                af[mt][0] = As[m * ROW_W + kb + t];
                af[mt][1] = As[(m + 8) * ROW_W + kb + t];
                af[mt][2] = As[m * ROW_W + kb + t + 4];
                af[mt][3] = As[(m + 8) * ROW_W + kb + t + 4];
            }
            #pragma unroll
            for (int nt = 0; nt < 8; nt++) {
                const int n = wn + nt * 8 + g;
                bf[nt][0] = Bs[n * ROW_W + kb + t];
                bf[nt][1] = Bs[n * ROW_W + kb + t + 4];
            }
            #pragma unroll
            for (int mt = 0; mt < 4; mt++)
                #pragma unroll
                for (int nt = 0; nt < 8; nt++)
                    mma_tf32(acc[mt][nt], af[mt], bf[nt][0], bf[nt][1]);
        }
    }

    // ---- epilogue ----
    const float lr = 0.1f;
    #pragma unroll
    for (int mt = 0; mt < 4; mt++) {
        #pragma unroll
        for (int nt = 0; nt < 8; nt++) {
            const int rA = row0 + wm + mt * 16 + g;
            const int rB = rA + 8;
            const int c  = col0 + wn + nt * 8 + t * 2;
            const size_t iA = (size_t)rA * N + c;
            const size_t iB = (size_t)rB * N + c;
            const float* v = acc[mt][nt];
            float2 oA, oB;
            if (sg.op == OP_FWD) {
                const float b0v = sg.aux[c], b1v = sg.aux[c + 1];
                oA = make_float2(tanhf(v[0] + b0v), tanhf(v[1] + b1v));
                oB = make_float2(tanhf(v[2] + b0v), tanhf(v[3] + b1v));
            } else if (sg.op == OP_ERR) {
                float2 xA = *(const float2*)&sg.aux[iA];
                float2 xB = *(const float2*)&sg.aux[iB];
                oA = make_float2(xA.x - tanhf(v[0]), xA.y - tanhf(v[1]));
                oB = make_float2(xB.x - tanhf(v[2]), xB.y - tanhf(v[3]));
            } else if (sg.op == OP_UPD) {
                float2 pA = *(const float2*)&sg.Out[iA];
                float2 pB = *(const float2*)&sg.Out[iB];
                float2 eA = *(const float2*)&sg.aux[iA];
                float2 eB = *(const float2*)&sg.aux[iB];
                oA = make_float2(pA.x + lr * (v[0] - eA.x), pA.y + lr * (v[1] - eA.y));
                oB = make_float2(pB.x + lr * (v[2] - eB.x), pB.y + lr * (v[3] - eB.y));
            } else { // OP_UPD3
                float2 pA = *(const float2*)&sg.Out[iA];
                float2 pB = *(const float2*)&sg.Out[iB];
                oA = make_float2(pA.x + lr * (v[0] - pA.x), pA.y + lr * (v[1] - pA.y));
                oB = make_float2(pB.x + lr * (v[2] - pB.x), pB.y + lr * (v[3] - pB.y));
            }
            *(float2*)&sg.Out[iA] = oA;
            *(float2*)&sg.Out[iB] = oB;
            *(float2*)&sg.OutR[iA] = make_float2(roundtf(oA.x), roundtf(oA.y));
            *(float2*)&sg.OutR[iB] = make_float2(roundtf(oB.x), roundtf(oB.y));
        }
    }
}

// ---------------- prep kernels ----------------
__global__ void round_copy(const float* __restrict__ s, float* __restrict__ d, int n)
{
    for (int i = blockIdx.x * blockDim.x + threadIdx.x; i < n;
         i += gridDim.x * blockDim.x)
        d[i] = roundtf(s[i]);
}

// T (C x R) = round(S (R x C)^T)
__global__ void transpose_round(const float* __restrict__ S, float* __restrict__ T,
                                int R, int C)
{
    __shared__ float t[32][33];
    const int x = blockIdx.x * 32 + threadIdx.x;
    const int y0 = blockIdx.y * 32;
    #pragma unroll
    for (int j = threadIdx.y; j < 32; j += 8)
        t[j][threadIdx.x] = S[(size_t)(y0 + j) * C + x];
    __syncthreads();
    const int x2 = y0 + threadIdx.x;
    #pragma unroll
    for (int j = threadIdx.y; j < 32; j += 8)
        T[(size_t)(blockIdx.x * 32 + j) * R + x2] = roundtf(t[threadIdx.x][j]);
}

// ---------------- reduction ----------------
__global__ void zero_acc_kernel() { g_acc = 0.0f; }

__global__ void sumsq_kernel(const float* __restrict__ x, int n)
{
    float s = 0.0f;
    for (int i = blockIdx.x * blockDim.x + threadIdx.x; i < n;
         i += gridDim.x * blockDim.x) {
        float v = x[i];
        s = fmaf(v, v, s);
    }
    #pragma unroll
    for (int o = 16; o > 0; o >>= 1) s += __shfl_down_sync(0xffffffffu, s, o);
    __shared__ float ws[32];
    const int lane = threadIdx.x & 31, w = threadIdx.x >> 5;
    if (lane == 0) ws[w] = s;
    __syncthreads();
    if (w == 0) {
        s = (lane < (int)(blockDim.x >> 5)) ? ws[lane] : 0.0f;
        #pragma unroll
        for (int o = 16; o > 0; o >>= 1) s += __shfl_down_sync(0xffffffffu, s, o);
        if (lane == 0) atomicAdd(&g_acc, s);
    }
}

__global__ void write_scalar_kernel(float* out)
{
    out[(size_t)BATCH * D3] = 0.5f * g_acc;
}

// ---------------- host ----------------
static inline Seg mkseg(const float* A, const float* B, const float* aux,
                        float* Out, float* OutR, int N, int K, int off, int op)
{
    Seg s;
    s.A = A; s.B = B; s.aux = aux; s.Out = Out; s.OutR = OutR;
    s.N = N; s.K = K; s.tileOff = off; s.tilesN = N / TN; s.op = op;
    return s;
}

#define MT (BATCH / TM)   // 16 M-tiles

extern "C" void kernel_launch(void* const* d_in, const int* in_sizes, int n_in,
                              void* d_out, int out_size)
{
    const float* x  = (const float*)d_in[0];
    const float* W0 = (const float*)d_in[1];
    const float* b0 = (const float*)d_in[2];
    const float* W1 = (const float*)d_in[3];
    const float* b1 = (const float*)d_in[4];
    const float* W2 = (const float*)d_in[5];
    const float* b2 = (const float*)d_in[6];
    float* out = (float*)d_out;

    float *r1, *r2, *r3, *e0, *e1, *e2;
    float *r1r, *r2r, *r3r, *e0r, *e1r, *e2r, *xr;
    float *W0r, *W1r, *W2r, *WT0r, *WT1r, *WT2r;
    cudaGetSymbolAddress((void**)&r1, g_r1);
    cudaGetSymbolAddress((void**)&r2, g_r2);
    cudaGetSymbolAddress((void**)&r3, g_r3);
    cudaGetSymbolAddress((void**)&e0, g_e0);
    cudaGetSymbolAddress((void**)&e1, g_e1);
    cudaGetSymbolAddress((void**)&e2, g_e2);
    cudaGetSymbolAddress((void**)&r1r, g_r1r);
    cudaGetSymbolAddress((void**)&r2r, g_r2r);
    cudaGetSymbolAddress((void**)&r3r, g_r3r);
    cudaGetSymbolAddress((void**)&e0r, g_e0r);
    cudaGetSymbolAddress((void**)&e1r, g_e1r);
    cudaGetSymbolAddress((void**)&e2r, g_e2r);
    cudaGetSymbolAddress((void**)&xr, g_xr);
    cudaGetSymbolAddress((void**)&W0r, g_W0r);
    cudaGetSymbolAddress((void**)&W1r, g_W1r);
    cudaGetSymbolAddress((void**)&W2r, g_W2r);
    cudaGetSymbolAddress((void**)&WT0r, g_WT0r);
    cudaGetSymbolAddress((void**)&WT1r, g_WT1r);
    cudaGetSymbolAddress((void**)&WT2r, g_WT2r);

    cudaFuncSetAttribute(gemm_fused, cudaFuncAttributeMaxDynamicSharedMemorySize,
                         SMEM_BYTES);

    const dim3 tblk(32, 8);

    // ---- prep: tf32-rounded weights / transposed weights / x ----
    round_copy<<<512, 256>>>(x,  xr,  BATCH * D0);
    round_copy<<<512, 256>>>(W0, W0r, D1 * D0);
    round_copy<<<512, 256>>>(W1, W1r, D2 * D1);
    round_copy<<<512, 256>>>(W2, W2r, D3 * D2);
    transpose_round<<<dim3(D0 / 32, D1 / 32), tblk>>>(W0, WT0r, D1, D0);
    transpose_round<<<dim3(D1 / 32, D2 / 32), tblk>>>(W1, WT1r, D2, D1);
    transpose_round<<<dim3(D2 / 32, D3 / 32), tblk>>>(W2, WT2r, D3, D2);

    // ---- feedforward init: r_{i+1} = tanh(r_i @ W_i^T + b_i) ----
    {
        FusedArgs a{}; a.nseg = 1;
        a.s[0] = mkseg(xr, W0r, b0, r1, r1r, D1, D0, 0, OP_FWD);
        gemm_fused<<<(D1 / TN) * MT, 256, SMEM_BYTES>>>(a);
    }
    {
        FusedArgs a{}; a.nseg = 1;
        a.s[0] = mkseg(r1r, W1r, b1, r2, r2r, D2, D1, 0, OP_FWD);
        gemm_fused<<<(D2 / TN) * MT, 256, SMEM_BYTES>>>(a);
    }
    {
        FusedArgs a{}; a.nseg = 1;
        a.s[0] = mkseg(r2r, W2r, b2, r3, r3r, D3, D2, 0, OP_FWD);
        gemm_fused<<<(D3 / TN) * MT, 256, SMEM_BYTES>>>(a);
    }

    // fused ERR (long-K segments first for wave balance):
    // e1 = r1 - tanh(r2@W1) [K=2048], e0 = x - tanh(r1@W0) [K=2048],
    // e2 = r2 - tanh(r3@W2) [K=512]
    FusedArgs ferr{}; ferr.nseg = 3;
    {
        int off = 0;
        ferr.s[0] = mkseg(r2r, WT1r, r1, e1, e1r, D1, D2, off, OP_ERR);
        off += (D1 / TN) * MT;
        ferr.s[1] = mkseg(r1r, WT0r, x, e0, e0r, D0, D1, off, OP_ERR);
        off += (D0 / TN) * MT;
        ferr.s[2] = mkseg(r3r, WT2r, r2, e2, e2r, D2, D3, off, OP_ERR);
    }
    const int errGrid = (D1 / TN) * MT + (D0 / TN) * MT + (D2 / TN) * MT;

    // fused UPD (long-K first):
    // r2 += lr*(e1@W1^T - e2) [K=2048], r3 += lr*(e2@W2^T - r3) [K=2048],
    // r1 += lr*(e0@W0^T - e1) [K=1024]
    FusedArgs fupd{}; fupd.nseg = 3;
    {
        int off = 0;
        fupd.s[0] = mkseg(e1r, W1r, e2, r2, r2r, D2, D1, off, OP_UPD);
        off += (D2 / TN) * MT;
        fupd.s[1] = mkseg(e2r, W2r, 0, r3, r3r, D3, D2, off, OP_UPD3);
        off += (D3 / TN) * MT;
        fupd.s[2] = mkseg(e0r, W0r, e1, r1, r1r, D1, D0, off, OP_UPD);
    }
    const int updGrid = (D2 / TN) * MT + (D3 / TN) * MT + (D1 / TN) * MT;

    // ---- 20 relaxation steps ----
    for (int s = 0; s < NSTEP; s++) {
        gemm_fused<<<errGrid, 256, SMEM_BYTES>>>(ferr);
        gemm_fused<<<updGrid, 256, SMEM_BYTES>>>(fupd);
    }

    // ---- final errors + total_error ----
    gemm_fused<<<errGrid, 256, SMEM_BYTES>>>(ferr);

    zero_acc_kernel<<<1, 1>>>();
    sumsq_kernel<<<1184, 256>>>(e0, BATCH * D0);
    sumsq_kernel<<<1184, 256>>>(e1, BATCH * D1);
    sumsq_kernel<<<1184, 256>>>(e2, BATCH * D2);
    sumsq_kernel<<<1184, 256>>>(r3, BATCH * D3);

    // ---- outputs: r3 flattened, then the scalar total_error ----
    cudaMemcpyAsync(out, r3, (size_t)BATCH * D3 * sizeof(float),
                    cudaMemcpyDeviceToDevice);
    if (out_size > BATCH * D3) {
        write_scalar_kernel<<<1, 1>>>(out);
    }
}